// round 4
// baseline (speedup 1.0000x reference)
#include <cuda_runtime.h>
#include <cstdint>

#define NB    2
#define N1V   4096
#define N2V   16384
#define CINV  512
#define CSKV  256
#define COUTV 256

// Scratch: h1 transposed [b][n1][co], knn idx/weights.
__device__ float g_h1T[(size_t)NB * N1V * COUTV];
__device__ int   g_idx[NB * N2V * 3];
__device__ float g_wgt[NB * N2V * 3];

// ---------------- cp.async helpers ----------------
__device__ __forceinline__ uint32_t s2u(const void* p) {
    return (uint32_t)__cvta_generic_to_shared(p);
}
__device__ __forceinline__ void cpa16(uint32_t dst, const void* src) {
    asm volatile("cp.async.cg.shared.global [%0], [%1], 16;\n" :: "r"(dst), "l"(src));
}
__device__ __forceinline__ void cpa_commit() {
    asm volatile("cp.async.commit_group;\n");
}
__device__ __forceinline__ void cpa_wait1() {
    asm volatile("cp.async.wait_group 1;\n");
}
__device__ __forceinline__ void cpa_wait0() {
    asm volatile("cp.async.wait_group 0;\n");
}

// ===========================================================================
// GEMM mainloop shared by conv1/conv2 (as a macro-like inline):
// tile 64co x 128n x 16k, 128 threads, 8co x 8n microtile, double-buffered.
// As[buf][co][k] (k contiguous, 8KB), Bs[buf][k][n] (16KB).
// Inner: per k-quad cache A in regs (8 broadcast LDS.128), then 4x(2 B LDS.128
// + 64 FFMA)  ->  FFMA:LDS = 16:1.
// ===========================================================================

// ---------------------------------------------------------------------------
// Fused front kernel: blocks [0,256) conv1, blocks [256,512) 3-NN.
// ---------------------------------------------------------------------------
__global__ __launch_bounds__(128, 3)
void front_kernel(const float* __restrict__ W1, const float* __restrict__ x1,
                  const float* __restrict__ g1, const float* __restrict__ b1,
                  const float* __restrict__ m1, const float* __restrict__ v1,
                  const float* __restrict__ p1, const float* __restrict__ p2)
{
    extern __shared__ char SRAW[];
    const int t   = threadIdx.x;
    const int bid = blockIdx.x;

    if (bid < 256) {
        // ------------------------- conv1 -------------------------
        float* AsB  = (float*)SRAW;              // buf*1024 + co*16 + k
        float* BsB  = (float*)(SRAW + 8192);     // buf*2048 + k*128 + n
        float* sc_s = (float*)(SRAW + 24576);
        float* sh_s = sc_s + 64;

        const int tx = t & 15;          // n micro: tx*8
        const int ty = t >> 4;          // co micro: ty*8
        const int n0  = (bid & 31) * 128;
        const int co0 = ((bid >> 5) & 3) * 64;
        const int bb  = bid >> 7;

        if (t < 64) {
            int co = co0 + t;
            float sc = g1[co] * rsqrtf(v1[co] + 1e-5f);
            sc_s[t] = sc;
            sh_s[t] = b1[co] - m1[co] * sc;
        }

        const float* xb = x1 + (size_t)bb * CINV * N1V;

        // cp.async roles (128 threads)
        const int a_co0 = t >> 2,        a_q0 = (t & 3) * 4;        // e = t
        const int a_co1 = (t + 128) >> 2, a_q1 = ((t + 128) & 3) * 4; // e = t+128
        const uint32_t sAbase = s2u(AsB);
        const uint32_t sBbase = s2u(BsB);
        const uint32_t sA0 = sAbase + (uint32_t)(a_co0 * 16 + a_q0) * 4u;
        const uint32_t sA1 = sAbase + (uint32_t)(a_co1 * 16 + a_q1) * 4u;
        const int b_col = (t & 31) * 4;
        const int b_rw0 = t >> 5;            // +0,4,8,12 for r=0..3
        uint32_t sB[4];
        #pragma unroll
        for (int r = 0; r < 4; r++)
            sB[r] = sBbase + (uint32_t)((b_rw0 + r * 4) * 128 + b_col) * 4u;

        float acc[8][8];
        #pragma unroll
        for (int i = 0; i < 8; i++)
            #pragma unroll
            for (int j = 0; j < 8; j++) acc[i][j] = 0.f;

        const int NCH = CINV / 16;      // 32

        // prologue
        cpa16(sA0, &W1[(size_t)(co0 + a_co0) * CINV + a_q0]);
        cpa16(sA1, &W1[(size_t)(co0 + a_co1) * CINV + a_q1]);
        #pragma unroll
        for (int r = 0; r < 4; r++)
            cpa16(sB[r], &xb[(size_t)(b_rw0 + r * 4) * N1V + n0 + b_col]);
        cpa_commit();

        for (int ch = 0; ch < NCH; ch++) {
            const int cur = ch & 1;
            if (ch + 1 < NCH) {
                const int nxt = cur ^ 1;
                const int k0  = (ch + 1) * 16;
                cpa16(sA0 + nxt * 4096u, &W1[(size_t)(co0 + a_co0) * CINV + k0 + a_q0]);
                cpa16(sA1 + nxt * 4096u, &W1[(size_t)(co0 + a_co1) * CINV + k0 + a_q1]);
                #pragma unroll
                for (int r = 0; r < 4; r++)
                    cpa16(sB[r] + nxt * 8192u,
                          &xb[(size_t)(k0 + b_rw0 + r * 4) * N1V + n0 + b_col]);
                cpa_commit();
                cpa_wait1();
            } else {
                cpa_wait0();
            }
            __syncthreads();

            const float* Ab = AsB + cur * 1024 + (ty * 8) * 16;
            const float* Bb = BsB + cur * 2048;
            #pragma unroll
            for (int kq = 0; kq < 4; kq++) {
                float af[8][4];
                #pragma unroll
                for (int i = 0; i < 8; i++) {
                    float4 v = *(const float4*)&Ab[i * 16 + kq * 4];
                    af[i][0] = v.x; af[i][1] = v.y; af[i][2] = v.z; af[i][3] = v.w;
                }
                #pragma unroll
                for (int k2 = 0; k2 < 4; k2++) {
                    const float* br = &Bb[(kq * 4 + k2) * 128 + tx * 8];
                    float4 b0 = *(const float4*)&br[0];
                    float4 b1q = *(const float4*)&br[4];
                    float bf[8] = {b0.x, b0.y, b0.z, b0.w, b1q.x, b1q.y, b1q.z, b1q.w};
                    #pragma unroll
                    for (int i = 0; i < 8; i++) {
                        float a = af[i][k2];
                        #pragma unroll
                        for (int j = 0; j < 8; j++)
                            acc[i][j] = fmaf(a, bf[j], acc[i][j]);
                    }
                }
            }
            __syncthreads();
        }

        float sc[8], sh[8];
        #pragma unroll
        for (int i = 0; i < 8; i++) {
            sc[i] = sc_s[ty * 8 + i];
            sh[i] = sh_s[ty * 8 + i];
        }
        #pragma unroll
        for (int j = 0; j < 8; j++) {
            int n = n0 + tx * 8 + j;
            float* dst = &g_h1T[((size_t)bb * N1V + n) * COUTV + co0 + ty * 8];
            float4 v0, v1q;
            v0.x  = fmaxf(fmaf(acc[0][j], sc[0], sh[0]), 0.f);
            v0.y  = fmaxf(fmaf(acc[1][j], sc[1], sh[1]), 0.f);
            v0.z  = fmaxf(fmaf(acc[2][j], sc[2], sh[2]), 0.f);
            v0.w  = fmaxf(fmaf(acc[3][j], sc[3], sh[3]), 0.f);
            v1q.x = fmaxf(fmaf(acc[4][j], sc[4], sh[4]), 0.f);
            v1q.y = fmaxf(fmaf(acc[5][j], sc[5], sh[5]), 0.f);
            v1q.z = fmaxf(fmaf(acc[6][j], sc[6], sh[6]), 0.f);
            v1q.w = fmaxf(fmaf(acc[7][j], sc[7], sh[7]), 0.f);
            *(float4*)&dst[0] = v0;
            *(float4*)&dst[4] = v1q;
        }
    } else {
        // ------------------------- knn (p1 tiled 2x2048 = 32KB) ------------
        float4* p1s = (float4*)SRAW;    // 2048 * 16B = 32 KB
        const int kbid = bid - 256;     // 0..255
        const int bb   = kbid >> 7;
        const int n2   = (kbid & 127) * 128 + t;

        const float* q = p2 + ((size_t)bb * N2V + n2) * 3;
        float qx = q[0], qy = q[1], qz = q[2];
        float q2 = fmaf(qx, qx, fmaf(qy, qy, qz * qz));
        float mx = -2.f * qx, my = -2.f * qy, mz = -2.f * qz;

        float s0 = 3.4e38f, s1 = 3.4e38f, s2 = 3.4e38f;
        int   i0 = 0,       i1 = 0,       i2 = 0;

        const float* p1b = p1 + (size_t)bb * N1V * 3;
        for (int tile = 0; tile < 2; tile++) {
            __syncthreads();
            const float* pt = p1b + tile * 2048 * 3;
            for (int e = t; e < 2048; e += 128) {
                float x = pt[e * 3 + 0], y = pt[e * 3 + 1], z = pt[e * 3 + 2];
                p1s[e] = make_float4(x, y, z, fmaf(x, x, fmaf(y, y, z * z)));
            }
            __syncthreads();
            const int jbase = tile * 2048;
            #pragma unroll 4
            for (int j = 0; j < 2048; j++) {
                float4 f = p1s[j];
                float s = fmaf(mx, f.x, f.w);
                s = fmaf(my, f.y, s);
                s = fmaf(mz, f.z, s);
                if (s < s2) {
                    int jj = jbase + j;
                    if (s < s1) {
                        s2 = s1; i2 = i1;
                        if (s < s0) { s1 = s0; i1 = i0; s0 = s; i0 = jj; }
                        else        { s1 = s;  i1 = jj; }
                    } else { s2 = s; i2 = jj; }
                }
            }
        }

        float r0 = 1.f / (s0 + q2 + 1e-8f);
        float r1 = 1.f / (s1 + q2 + 1e-8f);
        float r2 = 1.f / (s2 + q2 + 1e-8f);
        float inv = 1.f / (r0 + r1 + r2);

        int base = (bb * N2V + n2) * 3;
        g_idx[base + 0] = i0; g_idx[base + 1] = i1; g_idx[base + 2] = i2;
        g_wgt[base + 0] = r0 * inv; g_wgt[base + 1] = r1 * inv; g_wgt[base + 2] = r2 * inv;
    }
}

// ---------------------------------------------------------------------------
// conv2: y = relu(bn(W2@x2)) + 3-NN weighted gather of h1T. Same mainloop.
// ---------------------------------------------------------------------------
__global__ __launch_bounds__(128, 3)
void conv2_kernel(const float* __restrict__ W2, const float* __restrict__ x2,
                  const float* __restrict__ g2, const float* __restrict__ b2,
                  const float* __restrict__ m2, const float* __restrict__ v2,
                  float* __restrict__ yout)
{
    __shared__ float AsB[2 * 64 * 16];     // buf*1024 + co*16 + k
    __shared__ float BsB[2 * 16 * 128];    // buf*2048 + k*128 + n
    __shared__ float sc_s[64], sh_s[64];
    __shared__ int   idx_s[384];
    __shared__ float w_s[384];

    const int t  = threadIdx.x;
    const int tx = t & 15;
    const int ty = t >> 4;
    const int n0  = blockIdx.x * 128;
    const int co0 = blockIdx.y * 64;
    const int bb  = blockIdx.z;

    if (t < 64) {
        int co = co0 + t;
        float sc = g2[co] * rsqrtf(v2[co] + 1e-5f);
        sc_s[t] = sc;
        sh_s[t] = b2[co] - m2[co] * sc;
    }
    {
        int base = (bb * N2V + n0) * 3;
        for (int u = t; u < 384; u += 128) {
            idx_s[u] = g_idx[base + u];
            w_s[u]   = g_wgt[base + u];
        }
    }

    const float* xb = x2 + (size_t)bb * CSKV * N2V;

    const int a_co0 = t >> 2,         a_q0 = (t & 3) * 4;
    const int a_co1 = (t + 128) >> 2, a_q1 = ((t + 128) & 3) * 4;
    const uint32_t sAbase = s2u(AsB);
    const uint32_t sBbase = s2u(BsB);
    const uint32_t sA0 = sAbase + (uint32_t)(a_co0 * 16 + a_q0) * 4u;
    const uint32_t sA1 = sAbase + (uint32_t)(a_co1 * 16 + a_q1) * 4u;
    const int b_col = (t & 31) * 4;
    const int b_rw0 = t >> 5;
    uint32_t sB[4];
    #pragma unroll
    for (int r = 0; r < 4; r++)
        sB[r] = sBbase + (uint32_t)((b_rw0 + r * 4) * 128 + b_col) * 4u;

    float acc[8][8];
    #pragma unroll
    for (int i = 0; i < 8; i++)
        #pragma unroll
        for (int j = 0; j < 8; j++) acc[i][j] = 0.f;

    const int NCH = CSKV / 16;   // 16

    cpa16(sA0, &W2[(size_t)(co0 + a_co0) * CSKV + a_q0]);
    cpa16(sA1, &W2[(size_t)(co0 + a_co1) * CSKV + a_q1]);
    #pragma unroll
    for (int r = 0; r < 4; r++)
        cpa16(sB[r], &xb[(size_t)(b_rw0 + r * 4) * N2V + n0 + b_col]);
    cpa_commit();

    for (int ch = 0; ch < NCH; ch++) {
        const int cur = ch & 1;
        if (ch + 1 < NCH) {
            const int nxt = cur ^ 1;
            const int k0  = (ch + 1) * 16;
            cpa16(sA0 + nxt * 4096u, &W2[(size_t)(co0 + a_co0) * CSKV + k0 + a_q0]);
            cpa16(sA1 + nxt * 4096u, &W2[(size_t)(co0 + a_co1) * CSKV + k0 + a_q1]);
            #pragma unroll
            for (int r = 0; r < 4; r++)
                cpa16(sB[r] + nxt * 8192u,
                      &xb[(size_t)(k0 + b_rw0 + r * 4) * N2V + n0 + b_col]);
            cpa_commit();
            cpa_wait1();
        } else {
            cpa_wait0();
        }
        __syncthreads();

        const float* Ab = AsB + cur * 1024 + (ty * 8) * 16;
        const float* Bb = BsB + cur * 2048;
        #pragma unroll
        for (int kq = 0; kq < 4; kq++) {
            float af[8][4];
            #pragma unroll
            for (int i = 0; i < 8; i++) {
                float4 v = *(const float4*)&Ab[i * 16 + kq * 4];
                af[i][0] = v.x; af[i][1] = v.y; af[i][2] = v.z; af[i][3] = v.w;
            }
            #pragma unroll
            for (int k2 = 0; k2 < 4; k2++) {
                const float* br = &Bb[(kq * 4 + k2) * 128 + tx * 8];
                float4 b0 = *(const float4*)&br[0];
                float4 b1q = *(const float4*)&br[4];
                float bf[8] = {b0.x, b0.y, b0.z, b0.w, b1q.x, b1q.y, b1q.z, b1q.w};
                #pragma unroll
                for (int i = 0; i < 8; i++) {
                    float a = af[i][k2];
                    #pragma unroll
                    for (int j = 0; j < 8; j++)
                        acc[i][j] = fmaf(a, bf[j], acc[i][j]);
                }
            }
        }
        __syncthreads();
    }

    // BN + ReLU (conv branch only)
    float sc[8], sh[8];
    #pragma unroll
    for (int i = 0; i < 8; i++) {
        sc[i] = sc_s[ty * 8 + i];
        sh[i] = sh_s[ty * 8 + i];
    }
    #pragma unroll
    for (int i = 0; i < 8; i++)
        #pragma unroll
        for (int j = 0; j < 8; j++)
            acc[i][j] = fmaxf(fmaf(acc[i][j], sc[i], sh[i]), 0.f);

    // + interpolated upsample: 3-neighbor weighted gather from h1T (co-contig)
    #pragma unroll
    for (int j = 0; j < 8; j++) {
        int cj = tx * 8 + j;
        #pragma unroll
        for (int k = 0; k < 3; k++) {
            int   id = idx_s[cj * 3 + k];
            float w  = w_s[cj * 3 + k];
            const float* src = &g_h1T[((size_t)bb * N1V + id) * COUTV + co0 + ty * 8];
            float4 gA = *(const float4*)&src[0];
            float4 gB = *(const float4*)&src[4];
            acc[0][j] = fmaf(w, gA.x, acc[0][j]);
            acc[1][j] = fmaf(w, gA.y, acc[1][j]);
            acc[2][j] = fmaf(w, gA.z, acc[2][j]);
            acc[3][j] = fmaf(w, gA.w, acc[3][j]);
            acc[4][j] = fmaf(w, gB.x, acc[4][j]);
            acc[5][j] = fmaf(w, gB.y, acc[5][j]);
            acc[6][j] = fmaf(w, gB.z, acc[6][j]);
            acc[7][j] = fmaf(w, gB.w, acc[7][j]);
        }
    }

    // store y[b][co][n] (lanes cover consecutive 32B spans -> coalesced)
    #pragma unroll
    for (int i = 0; i < 8; i++) {
        int co = co0 + ty * 8 + i;
        float* drow = &yout[((size_t)(bb * COUTV + co)) * N2V + n0 + tx * 8];
        *(float4*)&drow[0] = make_float4(acc[i][0], acc[i][1], acc[i][2], acc[i][3]);
        *(float4*)&drow[4] = make_float4(acc[i][4], acc[i][5], acc[i][6], acc[i][7]);
    }
}

// ---------------------------------------------------------------------------
extern "C" void kernel_launch(void* const* d_in, const int* in_sizes, int n_in,
                              void* d_out, int out_size)
{
    const float* p1 = (const float*)d_in[0];
    const float* x1 = (const float*)d_in[1];
    const float* p2 = (const float*)d_in[2];
    const float* x2 = (const float*)d_in[3];
    const float* W1 = (const float*)d_in[4];
    const float* g1 = (const float*)d_in[5];
    const float* b1 = (const float*)d_in[6];
    const float* m1 = (const float*)d_in[7];
    const float* v1 = (const float*)d_in[8];
    const float* W2 = (const float*)d_in[9];
    const float* g2 = (const float*)d_in[10];
    const float* b2 = (const float*)d_in[11];
    const float* m2 = (const float*)d_in[12];
    const float* v2 = (const float*)d_in[13];

    float* out = (float*)d_out;
    const int P2SZ = NB * N2V * 3;
    const int YSZ  = NB * COUTV * N2V;

    float* yout = out;
    if (out_size == P2SZ + YSZ) {
        cudaMemcpyAsync(out, p2, (size_t)P2SZ * sizeof(float),
                        cudaMemcpyDeviceToDevice);
        yout = out + P2SZ;
    }

    cudaFuncSetAttribute(front_kernel,
                         cudaFuncAttributeMaxDynamicSharedMemorySize, 32768);

    // 256 conv1 blocks + 256 knn blocks, co-resident (overlapped)
    front_kernel<<<512, 128, 32768>>>(W1, x1, g1, b1, m1, v1, p1, p2);
    conv2_kernel<<<dim3(N2V / 128, COUTV / 64, NB), 128>>>(W2, x2, g2, b2, m2, v2, yout);
}

// round 6
// speedup vs baseline: 1.0804x; 1.0804x over previous
#include <cuda_runtime.h>
#include <cstdint>

#define NB    2
#define N1V   4096
#define N2V   16384
#define CINV  512
#define CSKV  256
#define COUTV 256

// Scratch: h1 transposed [b][n1][co], knn idx/weights, pre-transposed weights.
__device__ float g_h1T[(size_t)NB * N1V * COUTV];
__device__ int   g_idx[NB * N2V * 3];
__device__ float g_wgt[NB * N2V * 3];
__device__ float g_WT1[CINV * COUTV];   // WT1[k][co] = W1[co][k] * sc1[co]
__device__ float g_WT2[CSKV * COUTV];   // WT2[k][co] = W2[co][k] * sc2[co]

// ---------------- cp.async helpers ----------------
__device__ __forceinline__ uint32_t s2u(const void* p) {
    return (uint32_t)__cvta_generic_to_shared(p);
}
__device__ __forceinline__ void cpa16(uint32_t dst, const void* src) {
    asm volatile("cp.async.cg.shared.global [%0], [%1], 16;\n" :: "r"(dst), "l"(src));
}
__device__ __forceinline__ void cpa_commit() {
    asm volatile("cp.async.commit_group;\n");
}
__device__ __forceinline__ void cpa_wait1() {
    asm volatile("cp.async.wait_group 1;\n");
}
__device__ __forceinline__ void cpa_wait0() {
    asm volatile("cp.async.wait_group 0;\n");
}

// ===========================================================================
// Prologue: transpose W (and fold BN scale) into WT[k][co].
// blockIdx.z: 0 -> W1 (Cin=512), 1 -> W2 (Cin=256). 32x32 tiles, 256 thr.
// ===========================================================================
__global__ __launch_bounds__(256)
void wtrans_kernel(const float* __restrict__ W1, const float* __restrict__ g1,
                   const float* __restrict__ v1,
                   const float* __restrict__ W2, const float* __restrict__ g2,
                   const float* __restrict__ v2)
{
    __shared__ float tile[32][33];
    const int which = blockIdx.z;
    const int Cin   = which ? CSKV : CINV;
    if (blockIdx.y * 32 >= Cin) return;
    const float* W  = which ? W2 : W1;
    const float* g  = which ? g2 : g1;
    const float* v  = which ? v2 : v1;
    float* WT       = which ? g_WT2 : g_WT1;

    const int co0 = blockIdx.x * 32;
    const int k0  = blockIdx.y * 32;
    const int lx  = threadIdx.x & 31;
    const int ly  = threadIdx.x >> 5;   // 0..7

    #pragma unroll
    for (int r = 0; r < 4; r++)
        tile[ly + r * 8][lx] = W[(size_t)(co0 + ly + r * 8) * Cin + k0 + lx];
    __syncthreads();

    const float sc = g[co0 + lx] * rsqrtf(v[co0 + lx] + 1e-5f);
    #pragma unroll
    for (int r = 0; r < 4; r++)
        WT[(size_t)(k0 + ly + r * 8) * COUTV + co0 + lx] =
            tile[lx][ly + r * 8] * sc;
}

// ===========================================================================
// GEMM mainloop (both convs): tile 64co x 128n x 16k, 128 thr, 8x8 microtile.
// As[buf][k][64co] (co contig), Bs[buf][k][128n]. Per kk: 4 LDS.128 + 64 FFMA.
// ===========================================================================
#define GEMM_MAINLOOP(WTSRC, XB, NSTRIDE, NCHUNKS)                              \
    const int a_row = t >> 4, a_c4 = (t & 15) * 4;   /* 2 float4/thread */       \
    const uint32_t sA0 = s2u(AsB) + (uint32_t)(a_row * 64 + a_c4) * 4u;          \
    const uint32_t sA1 = s2u(AsB) + (uint32_t)((a_row + 8) * 64 + a_c4) * 4u;    \
    const int b_col = (t & 31) * 4;                                              \
    const int b_rw  = t >> 5;                                                    \
    uint32_t sB[4];                                                              \
    _Pragma("unroll")                                                            \
    for (int r = 0; r < 4; r++)                                                  \
        sB[r] = s2u(BsB) + (uint32_t)((b_rw + r * 4) * 128 + b_col) * 4u;        \
    float acc[8][8];                                                             \
    _Pragma("unroll")                                                            \
    for (int i = 0; i < 8; i++)                                                  \
        _Pragma("unroll")                                                        \
        for (int j = 0; j < 8; j++) acc[i][j] = 0.f;                             \
    cpa16(sA0, &WTSRC[(size_t)a_row * COUTV + co0 + a_c4]);                      \
    cpa16(sA1, &WTSRC[(size_t)(a_row + 8) * COUTV + co0 + a_c4]);                \
    _Pragma("unroll")                                                            \
    for (int r = 0; r < 4; r++)                                                  \
        cpa16(sB[r], &XB[(size_t)(b_rw + r * 4) * NSTRIDE + n0 + b_col]);        \
    cpa_commit();                                                                \
    for (int ch = 0; ch < NCHUNKS; ch++) {                                       \
        const int cur = ch & 1;                                                  \
        if (ch + 1 < NCHUNKS) {                                                  \
            const int nxt = cur ^ 1;                                             \
            const int k0n = (ch + 1) * 16;                                       \
            cpa16(sA0 + nxt * 4096u, &WTSRC[(size_t)(k0n + a_row) * COUTV + co0 + a_c4]);      \
            cpa16(sA1 + nxt * 4096u, &WTSRC[(size_t)(k0n + a_row + 8) * COUTV + co0 + a_c4]);  \
            _Pragma("unroll")                                                    \
            for (int r = 0; r < 4; r++)                                          \
                cpa16(sB[r] + nxt * 8192u,                                       \
                      &XB[(size_t)(k0n + b_rw + r * 4) * NSTRIDE + n0 + b_col]); \
            cpa_commit();                                                        \
            cpa_wait1();                                                         \
        } else {                                                                 \
            cpa_wait0();                                                         \
        }                                                                        \
        __syncthreads();                                                         \
        const float* Ab = AsB + cur * 1024;                                      \
        const float* Bb = BsB + cur * 2048;                                      \
        _Pragma("unroll")                                                        \
        for (int kk = 0; kk < 16; kk++) {                                        \
            float4 a0 = *(const float4*)&Ab[kk * 64 + ty * 8];                   \
            float4 a1 = *(const float4*)&Ab[kk * 64 + ty * 8 + 4];               \
            float4 b0 = *(const float4*)&Bb[kk * 128 + tx * 8];                  \
            float4 b1 = *(const float4*)&Bb[kk * 128 + tx * 8 + 4];              \
            float av[8] = {a0.x, a0.y, a0.z, a0.w, a1.x, a1.y, a1.z, a1.w};      \
            float bv[8] = {b0.x, b0.y, b0.z, b0.w, b1.x, b1.y, b1.z, b1.w};      \
            _Pragma("unroll")                                                    \
            for (int i = 0; i < 8; i++)                                          \
                _Pragma("unroll")                                                \
                for (int j = 0; j < 8; j++)                                      \
                    acc[i][j] = fmaf(av[i], bv[j], acc[i][j]);                   \
        }                                                                        \
        __syncthreads();                                                         \
    }

// ---------------------------------------------------------------------------
// Fused front kernel: blocks [0,256) conv1, blocks [256,512) 3-NN.
// ---------------------------------------------------------------------------
__global__ __launch_bounds__(128, 4)
void front_kernel(const float* __restrict__ x1,
                  const float* __restrict__ b1, const float* __restrict__ m1,
                  const float* __restrict__ g1, const float* __restrict__ v1,
                  const float* __restrict__ p1, const float* __restrict__ p2)
{
    extern __shared__ char SRAW[];
    const int t   = threadIdx.x;
    const int bid = blockIdx.x;

    if (bid < 256) {
        // ------------------------- conv1 -------------------------
        float* AsB  = (float*)SRAW;              // [buf][k][64]  8KB
        float* BsB  = (float*)(SRAW + 8192);     // [buf][k][128] 16KB
        float* sh_s = (float*)(SRAW + 24576);    // 64 floats

        const int tx = t & 15;          // n micro: tx*8
        const int ty = t >> 4;          // co micro: ty*8
        const int n0  = (bid & 31) * 128;
        const int co0 = ((bid >> 5) & 3) * 64;
        const int bb  = bid >> 7;

        if (t < 64) {
            int co = co0 + t;
            sh_s[t] = b1[co] - m1[co] * (g1[co] * rsqrtf(v1[co] + 1e-5f));
        }

        const float* xb = x1 + (size_t)bb * CINV * N1V;

        GEMM_MAINLOOP(g_WT1, xb, N1V, (CINV / 16))

        float sh[8];
        #pragma unroll
        for (int i = 0; i < 8; i++) sh[i] = sh_s[ty * 8 + i];

        #pragma unroll
        for (int j = 0; j < 8; j++) {
            int n = n0 + tx * 8 + j;
            float* dst = &g_h1T[((size_t)bb * N1V + n) * COUTV + co0 + ty * 8];
            float4 v0, v1q;
            v0.x  = fmaxf(acc[0][j] + sh[0], 0.f);
            v0.y  = fmaxf(acc[1][j] + sh[1], 0.f);
            v0.z  = fmaxf(acc[2][j] + sh[2], 0.f);
            v0.w  = fmaxf(acc[3][j] + sh[3], 0.f);
            v1q.x = fmaxf(acc[4][j] + sh[4], 0.f);
            v1q.y = fmaxf(acc[5][j] + sh[5], 0.f);
            v1q.z = fmaxf(acc[6][j] + sh[6], 0.f);
            v1q.w = fmaxf(acc[7][j] + sh[7], 0.f);
            *(float4*)&dst[0] = v0;
            *(float4*)&dst[4] = v1q;
        }
    } else {
        // ------------------------- knn (p1 tiled 2x2048 = 32KB) ------------
        float4* p1s = (float4*)SRAW;
        const int kbid = bid - 256;     // 0..255
        const int bb   = kbid >> 7;
        const int n2   = (kbid & 127) * 128 + t;

        const float* q = p2 + ((size_t)bb * N2V + n2) * 3;
        float qx = q[0], qy = q[1], qz = q[2];
        float q2 = fmaf(qx, qx, fmaf(qy, qy, qz * qz));
        float mx = -2.f * qx, my = -2.f * qy, mz = -2.f * qz;

        float s0 = 3.4e38f, s1 = 3.4e38f, s2 = 3.4e38f;
        int   i0 = 0,       i1 = 0,       i2 = 0;

        const float* p1b = p1 + (size_t)bb * N1V * 3;
        for (int tile = 0; tile < 2; tile++) {
            __syncthreads();
            const float* pt = p1b + tile * 2048 * 3;
            for (int e = t; e < 2048; e += 128) {
                float x = pt[e * 3 + 0], y = pt[e * 3 + 1], z = pt[e * 3 + 2];
                p1s[e] = make_float4(x, y, z, fmaf(x, x, fmaf(y, y, z * z)));
            }
            __syncthreads();
            const int jbase = tile * 2048;
            #pragma unroll 4
            for (int j = 0; j < 2048; j++) {
                float4 f = p1s[j];
                float s = fmaf(mx, f.x, f.w);
                s = fmaf(my, f.y, s);
                s = fmaf(mz, f.z, s);
                if (s < s2) {
                    int jj = jbase + j;
                    if (s < s1) {
                        s2 = s1; i2 = i1;
                        if (s < s0) { s1 = s0; i1 = i0; s0 = s; i0 = jj; }
                        else        { s1 = s;  i1 = jj; }
                    } else { s2 = s; i2 = jj; }
                }
            }
        }

        float r0 = 1.f / (s0 + q2 + 1e-8f);
        float r1 = 1.f / (s1 + q2 + 1e-8f);
        float r2 = 1.f / (s2 + q2 + 1e-8f);
        float inv = 1.f / (r0 + r1 + r2);

        int base = (bb * N2V + n2) * 3;
        g_idx[base + 0] = i0; g_idx[base + 1] = i1; g_idx[base + 2] = i2;
        g_wgt[base + 0] = r0 * inv; g_wgt[base + 1] = r1 * inv; g_wgt[base + 2] = r2 * inv;
    }
}

// ---------------------------------------------------------------------------
// conv2: y = relu(WT2s@x2 + shift) + 3-NN weighted gather of h1T.
// ---------------------------------------------------------------------------
__global__ __launch_bounds__(128, 4)
void conv2_kernel(const float* __restrict__ x2,
                  const float* __restrict__ b2, const float* __restrict__ m2,
                  const float* __restrict__ g2, const float* __restrict__ v2,
                  float* __restrict__ yout)
{
    __shared__ float AsB[2 * 16 * 64];
    __shared__ float BsB[2 * 16 * 128];
    __shared__ float sh_s[64];
    __shared__ int   idx_s[384];
    __shared__ float w_s[384];

    const int t  = threadIdx.x;
    const int tx = t & 15;
    const int ty = t >> 4;
    const int n0  = blockIdx.x * 128;
    const int co0 = blockIdx.y * 64;
    const int bb  = blockIdx.z;

    if (t < 64) {
        int co = co0 + t;
        sh_s[t] = b2[co] - m2[co] * (g2[co] * rsqrtf(v2[co] + 1e-5f));
    }
    {
        int base = (bb * N2V + n0) * 3;
        for (int u = t; u < 384; u += 128) {
            idx_s[u] = g_idx[base + u];
            w_s[u]   = g_wgt[base + u];
        }
    }

    const float* xb = x2 + (size_t)bb * CSKV * N2V;

    GEMM_MAINLOOP(g_WT2, xb, N2V, (CSKV / 16))

    float sh[8];
    #pragma unroll
    for (int i = 0; i < 8; i++) sh[i] = sh_s[ty * 8 + i];
    #pragma unroll
    for (int i = 0; i < 8; i++)
        #pragma unroll
        for (int j = 0; j < 8; j++)
            acc[i][j] = fmaxf(acc[i][j] + sh[i], 0.f);

    // + interpolated upsample: 3-neighbor weighted gather from h1T (co-contig)
    #pragma unroll
    for (int j = 0; j < 8; j++) {
        int cj = tx * 8 + j;
        #pragma unroll
        for (int k = 0; k < 3; k++) {
            int   id = idx_s[cj * 3 + k];
            float w  = w_s[cj * 3 + k];
            const float* src = &g_h1T[((size_t)bb * N1V + id) * COUTV + co0 + ty * 8];
            float4 gA = *(const float4*)&src[0];
            float4 gB = *(const float4*)&src[4];
            acc[0][j] = fmaf(w, gA.x, acc[0][j]);
            acc[1][j] = fmaf(w, gA.y, acc[1][j]);
            acc[2][j] = fmaf(w, gA.z, acc[2][j]);
            acc[3][j] = fmaf(w, gA.w, acc[3][j]);
            acc[4][j] = fmaf(w, gB.x, acc[4][j]);
            acc[5][j] = fmaf(w, gB.y, acc[5][j]);
            acc[6][j] = fmaf(w, gB.z, acc[6][j]);
            acc[7][j] = fmaf(w, gB.w, acc[7][j]);
        }
    }

    // store y[b][co][n]
    #pragma unroll
    for (int i = 0; i < 8; i++) {
        int co = co0 + ty * 8 + i;
        float* drow = &yout[((size_t)(bb * COUTV + co)) * N2V + n0 + tx * 8];
        *(float4*)&drow[0] = make_float4(acc[i][0], acc[i][1], acc[i][2], acc[i][3]);
        *(float4*)&drow[4] = make_float4(acc[i][4], acc[i][5], acc[i][6], acc[i][7]);
    }
}

// ---------------------------------------------------------------------------
extern "C" void kernel_launch(void* const* d_in, const int* in_sizes, int n_in,
                              void* d_out, int out_size)
{
    const float* p1 = (const float*)d_in[0];
    const float* x1 = (const float*)d_in[1];
    const float* p2 = (const float*)d_in[2];
    const float* x2 = (const float*)d_in[3];
    const float* W1 = (const float*)d_in[4];
    const float* g1 = (const float*)d_in[5];
    const float* b1 = (const float*)d_in[6];
    const float* m1 = (const float*)d_in[7];
    const float* v1 = (const float*)d_in[8];
    const float* W2 = (const float*)d_in[9];
    const float* g2 = (const float*)d_in[10];
    const float* b2 = (const float*)d_in[11];
    const float* m2 = (const float*)d_in[12];
    const float* v2 = (const float*)d_in[13];

    float* out = (float*)d_out;
    const int P2SZ = NB * N2V * 3;
    const int YSZ  = NB * COUTV * N2V;

    float* yout = out;
    if (out_size == P2SZ + YSZ) {
        cudaMemcpyAsync(out, p2, (size_t)P2SZ * sizeof(float),
                        cudaMemcpyDeviceToDevice);
        yout = out + P2SZ;
    }

    cudaFuncSetAttribute(front_kernel,
                         cudaFuncAttributeMaxDynamicSharedMemorySize, 32768);

    wtrans_kernel<<<dim3(COUTV / 32, CINV / 32, 2), 256>>>(W1, g1, v1, W2, g2, v2);
    front_kernel<<<512, 128, 32768>>>(x1, b1, m1, g1, v1, p1, p2);
    conv2_kernel<<<dim3(N2V / 128, COUTV / 64, NB), 128>>>(x2, b2, m2, g2, v2, yout);
}

// round 7
// speedup vs baseline: 1.5858x; 1.4677x over previous
#include <cuda_runtime.h>
#include <cstdint>

#define NB    2
#define N1V   4096
#define N2V   16384
#define CINV  512
#define CSKV  256
#define COUTV 256

#define AS_STRIDE 72    // words; (8*tg+g)%32 distinct -> conflict-free frags
#define BS_STRIDE 136
#define AS_BUF_BYTES (16 * AS_STRIDE * 4)   // 4608
#define BS_BUF_BYTES (16 * BS_STRIDE * 4)   // 8704
#define PIPE_BYTES   (2 * AS_BUF_BYTES + 2 * BS_BUF_BYTES)  // 26624

// Scratch: h1 transposed [b][n1][co], knn idx/weights, tf32 weights WT[k][co].
__device__ float g_h1T[(size_t)NB * N1V * COUTV];
__device__ int   g_idx[NB * N2V * 3];
__device__ float g_wgt[NB * N2V * 3];
__device__ float g_WT1[CINV * COUTV];
__device__ float g_WT2[CSKV * COUTV];

// ---------------- helpers ----------------
__device__ __forceinline__ uint32_t s2u(const void* p) {
    return (uint32_t)__cvta_generic_to_shared(p);
}
__device__ __forceinline__ void cpa16(uint32_t dst, const void* src) {
    asm volatile("cp.async.cg.shared.global [%0], [%1], 16;\n" :: "r"(dst), "l"(src));
}
__device__ __forceinline__ void cpa_commit() {
    asm volatile("cp.async.commit_group;\n");
}
__device__ __forceinline__ void cpa_wait1() {
    asm volatile("cp.async.wait_group 1;\n");
}
__device__ __forceinline__ void cpa_wait0() {
    asm volatile("cp.async.wait_group 0;\n");
}
__device__ __forceinline__ uint32_t f2tf32(float x) {
    uint32_t u;
    asm("cvt.rna.tf32.f32 %0, %1;" : "=r"(u) : "f"(x));
    return u;
}
__device__ __forceinline__ void mma_tf32(float* c, const uint32_t* a,
                                         uint32_t b0, uint32_t b1) {
    asm volatile(
        "mma.sync.aligned.m16n8k8.row.col.f32.tf32.tf32.f32 "
        "{%0,%1,%2,%3}, {%4,%5,%6,%7}, {%8,%9}, {%0,%1,%2,%3};\n"
        : "+f"(c[0]), "+f"(c[1]), "+f"(c[2]), "+f"(c[3])
        : "r"(a[0]), "r"(a[1]), "r"(a[2]), "r"(a[3]), "r"(b0), "r"(b1));
}

// ===========================================================================
// Prologue: WT[k][co] = tf32_round( W[co][k] * bn_scale[co] )
// ===========================================================================
__global__ __launch_bounds__(256)
void wtrans_kernel(const float* __restrict__ W1, const float* __restrict__ g1,
                   const float* __restrict__ v1,
                   const float* __restrict__ W2, const float* __restrict__ g2,
                   const float* __restrict__ v2)
{
    __shared__ float tile[32][33];
    const int which = blockIdx.z;
    const int Cin   = which ? CSKV : CINV;
    if (blockIdx.y * 32 >= Cin) return;
    const float* W  = which ? W2 : W1;
    const float* g  = which ? g2 : g1;
    const float* v  = which ? v2 : v1;
    float* WT       = which ? g_WT2 : g_WT1;

    const int co0 = blockIdx.x * 32;
    const int k0  = blockIdx.y * 32;
    const int lx  = threadIdx.x & 31;
    const int ly  = threadIdx.x >> 5;

    #pragma unroll
    for (int r = 0; r < 4; r++)
        tile[ly + r * 8][lx] = W[(size_t)(co0 + ly + r * 8) * Cin + k0 + lx];
    __syncthreads();

    const float sc = g[co0 + lx] * rsqrtf(v[co0 + lx] + 1e-5f);
    #pragma unroll
    for (int r = 0; r < 4; r++)
        WT[(size_t)(k0 + ly + r * 8) * COUTV + co0 + lx] =
            __uint_as_float(f2tf32(tile[lx][ly + r * 8] * sc));
}

// ===========================================================================
// tf32 MMA mainloop: tile 64co x 128n x 16k, 128 thr (4 warps, 2co x 2n),
// warp tile 32co x 64n (2 x 8 m16n8k8 frags). Double-buffered cp.async.
// Produces acc[2][8][4]; thread element map:
//   co = cw + cf*16 + g + (e>=2? 8:0),  n = nw + nf*8 + 2*tg + (e&1)
// ===========================================================================
#define MMA_MAINLOOP(WTSRC, XB, NSTRIDE, NCHUNKS)                                \
    const int a_row = t >> 4, a_c4 = (t & 15) * 4;                               \
    const uint32_t sA0 = s2u(AsB) + (uint32_t)(a_row * AS_STRIDE + a_c4) * 4u;   \
    const uint32_t sA1 = s2u(AsB) + (uint32_t)((a_row + 8) * AS_STRIDE + a_c4) * 4u; \
    const int b_col = (t & 31) * 4;                                              \
    const int b_rw  = t >> 5;                                                    \
    uint32_t sB[4];                                                              \
    _Pragma("unroll")                                                            \
    for (int r = 0; r < 4; r++)                                                  \
        sB[r] = s2u(BsB) + (uint32_t)((b_rw + r * 4) * BS_STRIDE + b_col) * 4u;  \
    float acc[2][8][4];                                                          \
    _Pragma("unroll")                                                            \
    for (int cf = 0; cf < 2; cf++)                                               \
        _Pragma("unroll")                                                        \
        for (int nf = 0; nf < 8; nf++)                                           \
            _Pragma("unroll")                                                    \
            for (int e = 0; e < 4; e++) acc[cf][nf][e] = 0.f;                    \
    cpa16(sA0, &WTSRC[(size_t)a_row * COUTV + co0 + a_c4]);                      \
    cpa16(sA1, &WTSRC[(size_t)(a_row + 8) * COUTV + co0 + a_c4]);                \
    _Pragma("unroll")                                                            \
    for (int r = 0; r < 4; r++)                                                  \
        cpa16(sB[r], &XB[(size_t)(b_rw + r * 4) * NSTRIDE + n0 + b_col]);        \
    cpa_commit();                                                                \
    for (int ch = 0; ch < NCHUNKS; ch++) {                                       \
        const int cur = ch & 1;                                                  \
        if (ch + 1 < NCHUNKS) {                                                  \
            const int nxt = cur ^ 1;                                             \
            const int k0n = (ch + 1) * 16;                                       \
            cpa16(sA0 + nxt * AS_BUF_BYTES,                                      \
                  &WTSRC[(size_t)(k0n + a_row) * COUTV + co0 + a_c4]);           \
            cpa16(sA1 + nxt * AS_BUF_BYTES,                                      \
                  &WTSRC[(size_t)(k0n + a_row + 8) * COUTV + co0 + a_c4]);       \
            _Pragma("unroll")                                                    \
            for (int r = 0; r < 4; r++)                                          \
                cpa16(sB[r] + nxt * BS_BUF_BYTES,                                \
                      &XB[(size_t)(k0n + b_rw + r * 4) * NSTRIDE + n0 + b_col]); \
            cpa_commit();                                                        \
            cpa_wait1();                                                         \
        } else {                                                                 \
            cpa_wait0();                                                         \
        }                                                                        \
        __syncthreads();                                                         \
        const float* Ab = AsB + cur * (16 * AS_STRIDE);                          \
        const float* Bb = BsB + cur * (16 * BS_STRIDE);                          \
        _Pragma("unroll")                                                        \
        for (int s = 0; s < 2; s++) {                                            \
            const int kr0 = s * 8 + tg;                                          \
            uint32_t af[2][4];                                                   \
            _Pragma("unroll")                                                    \
            for (int cf = 0; cf < 2; cf++) {                                     \
                const int cb = cw + cf * 16 + g;                                 \
                af[cf][0] = __float_as_uint(Ab[kr0 * AS_STRIDE + cb]);           \
                af[cf][1] = __float_as_uint(Ab[kr0 * AS_STRIDE + cb + 8]);       \
                af[cf][2] = __float_as_uint(Ab[(kr0 + 4) * AS_STRIDE + cb]);     \
                af[cf][3] = __float_as_uint(Ab[(kr0 + 4) * AS_STRIDE + cb + 8]); \
            }                                                                    \
            _Pragma("unroll")                                                    \
            for (int nf = 0; nf < 8; nf++) {                                     \
                const int nn = nw + nf * 8 + g;                                  \
                uint32_t b0 = f2tf32(Bb[kr0 * BS_STRIDE + nn]);                  \
                uint32_t b1 = f2tf32(Bb[(kr0 + 4) * BS_STRIDE + nn]);            \
                mma_tf32(acc[0][nf], af[0], b0, b1);                             \
                mma_tf32(acc[1][nf], af[1], b0, b1);                             \
            }                                                                    \
        }                                                                        \
        __syncthreads();                                                         \
    }

// ---------------------------------------------------------------------------
// Fused front kernel: blocks [0,256) conv1 (tf32 MMA), blocks [256,512) 3-NN.
// ---------------------------------------------------------------------------
__global__ __launch_bounds__(128, 4)
void front_kernel(const float* __restrict__ x1,
                  const float* __restrict__ b1, const float* __restrict__ m1,
                  const float* __restrict__ g1, const float* __restrict__ v1,
                  const float* __restrict__ p1, const float* __restrict__ p2)
{
    extern __shared__ char SRAW[];
    const int t   = threadIdx.x;
    const int bid = blockIdx.x;

    if (bid < 256) {
        // ------------------------- conv1 -------------------------
        float* AsB  = (float*)SRAW;
        float* BsB  = (float*)(SRAW + 2 * AS_BUF_BYTES);
        float* sh_s = (float*)(SRAW + PIPE_BYTES);   // 64 floats

        const int lane = t & 31;
        const int g    = lane >> 2;
        const int tg   = lane & 3;
        const int warp = t >> 5;
        const int cw   = (warp >> 1) * 32;
        const int nw   = (warp & 1) * 64;

        const int n0  = (bid & 31) * 128;
        const int co0 = ((bid >> 5) & 3) * 64;
        const int bb  = bid >> 7;

        if (t < 64) {
            int co = co0 + t;
            sh_s[t] = b1[co] - m1[co] * (g1[co] * rsqrtf(v1[co] + 1e-5f));
        }

        const float* xb = x1 + (size_t)bb * CINV * N1V;

        MMA_MAINLOOP(g_WT1, xb, N1V, (CINV / 16))

        // epilogue: relu(acc + shift) -> h1T[b][n][co]  (scalar, sector-coalesced)
        #pragma unroll
        for (int cf = 0; cf < 2; cf++) {
            #pragma unroll
            for (int r = 0; r < 2; r++) {
                const int col = cw + cf * 16 + g + r * 8;
                const float sh = sh_s[col];
                const int co = co0 + col;
                #pragma unroll
                for (int nf = 0; nf < 8; nf++) {
                    const int n = n0 + nw + nf * 8 + 2 * tg;
                    float* dst = &g_h1T[((size_t)bb * N1V + n) * COUTV + co];
                    dst[0]     = fmaxf(acc[cf][nf][r * 2 + 0] + sh, 0.f);
                    dst[COUTV] = fmaxf(acc[cf][nf][r * 2 + 1] + sh, 0.f);
                }
            }
        }
    } else {
        // ------------------------- knn (p1 tiled 2x2048 = 32KB) ------------
        float4* p1s = (float4*)SRAW;
        const int kbid = bid - 256;
        const int bb   = kbid >> 7;
        const int n2   = (kbid & 127) * 128 + t;

        const float* q = p2 + ((size_t)bb * N2V + n2) * 3;
        float qx = q[0], qy = q[1], qz = q[2];
        float q2 = fmaf(qx, qx, fmaf(qy, qy, qz * qz));
        float mx = -2.f * qx, my = -2.f * qy, mz = -2.f * qz;

        float s0 = 3.4e38f, s1 = 3.4e38f, s2 = 3.4e38f;
        int   i0 = 0,       i1 = 0,       i2 = 0;

        const float* p1b = p1 + (size_t)bb * N1V * 3;
        for (int tile = 0; tile < 2; tile++) {
            __syncthreads();
            const float* pt = p1b + tile * 2048 * 3;
            for (int e = t; e < 2048; e += 128) {
                float x = pt[e * 3 + 0], y = pt[e * 3 + 1], z = pt[e * 3 + 2];
                p1s[e] = make_float4(x, y, z, fmaf(x, x, fmaf(y, y, z * z)));
            }
            __syncthreads();
            const int jbase = tile * 2048;
            #pragma unroll 4
            for (int j = 0; j < 2048; j++) {
                float4 f = p1s[j];
                float s = fmaf(mx, f.x, f.w);
                s = fmaf(my, f.y, s);
                s = fmaf(mz, f.z, s);
                if (s < s2) {
                    int jj = jbase + j;
                    if (s < s1) {
                        s2 = s1; i2 = i1;
                        if (s < s0) { s1 = s0; i1 = i0; s0 = s; i0 = jj; }
                        else        { s1 = s;  i1 = jj; }
                    } else { s2 = s; i2 = jj; }
                }
            }
        }

        float r0 = 1.f / (s0 + q2 + 1e-8f);
        float r1 = 1.f / (s1 + q2 + 1e-8f);
        float r2 = 1.f / (s2 + q2 + 1e-8f);
        float inv = 1.f / (r0 + r1 + r2);

        int base = (bb * N2V + n2) * 3;
        g_idx[base + 0] = i0; g_idx[base + 1] = i1; g_idx[base + 2] = i2;
        g_wgt[base + 0] = r0 * inv; g_wgt[base + 1] = r1 * inv; g_wgt[base + 2] = r2 * inv;
    }
}

// ---------------------------------------------------------------------------
// conv2: y = relu(tf32 GEMM + shift) + 3-NN weighted gather of h1T.
// Acc staged through smem so the gather/store reuses the float4 path.
// Dynamic smem layout: [0, 34816) pipeline bufs then staging (64 x 136 f32);
//                      [34816) idx_s (384 int), [36352) w_s (384 f), [37888) sh_s.
// ---------------------------------------------------------------------------
#define STAGE_STRIDE 136
__global__ __launch_bounds__(128, 4)
void conv2_kernel(const float* __restrict__ x2,
                  const float* __restrict__ b2, const float* __restrict__ m2,
                  const float* __restrict__ g2, const float* __restrict__ v2,
                  float* __restrict__ yout)
{
    extern __shared__ char SRAW[];
    float* AsB   = (float*)SRAW;
    float* BsB   = (float*)(SRAW + 2 * AS_BUF_BYTES);
    float* stage = (float*)SRAW;                    // reused after mainloop
    int*   idx_s = (int*)(SRAW + 34816);
    float* w_s   = (float*)(SRAW + 36352);
    float* sh_s  = (float*)(SRAW + 37888);

    const int t  = threadIdx.x;
    const int lane = t & 31;
    const int g    = lane >> 2;
    const int tg   = lane & 3;
    const int warp = t >> 5;
    const int cw   = (warp >> 1) * 32;
    const int nw   = (warp & 1) * 64;

    const int n0  = blockIdx.x * 128;
    const int co0 = blockIdx.y * 64;
    const int bb  = blockIdx.z;

    if (t < 64) {
        int co = co0 + t;
        sh_s[t] = b2[co] - m2[co] * (g2[co] * rsqrtf(v2[co] + 1e-5f));
    }
    {
        int base = (bb * N2V + n0) * 3;
        for (int u = t; u < 384; u += 128) {
            idx_s[u] = g_idx[base + u];
            w_s[u]   = g_wgt[base + u];
        }
    }

    const float* xb = x2 + (size_t)bb * CSKV * N2V;

    MMA_MAINLOOP(g_WT2, xb, N2V, (CSKV / 16))

    // stage raw acc -> smem [co_local][n_local] (float2 stores, n pairs)
    #pragma unroll
    for (int cf = 0; cf < 2; cf++) {
        #pragma unroll
        for (int r = 0; r < 2; r++) {
            const int col = cw + cf * 16 + g + r * 8;
            #pragma unroll
            for (int nf = 0; nf < 8; nf++) {
                const int nl = nw + nf * 8 + 2 * tg;
                *(float2*)&stage[col * STAGE_STRIDE + nl] =
                    make_float2(acc[cf][nf][r * 2], acc[cf][nf][r * 2 + 1]);
            }
        }
    }
    __syncthreads();

    // epilogue in the classic 8co x 8n per-thread pattern
    const int tx = t & 15;
    const int ty = t >> 4;

    float r_[8][8];
    #pragma unroll
    for (int i = 0; i < 8; i++) {
        const float sh = sh_s[ty * 8 + i];
        float4 vA = *(const float4*)&stage[(ty * 8 + i) * STAGE_STRIDE + tx * 8];
        float4 vB = *(const float4*)&stage[(ty * 8 + i) * STAGE_STRIDE + tx * 8 + 4];
        r_[i][0] = fmaxf(vA.x + sh, 0.f);
        r_[i][1] = fmaxf(vA.y + sh, 0.f);
        r_[i][2] = fmaxf(vA.z + sh, 0.f);
        r_[i][3] = fmaxf(vA.w + sh, 0.f);
        r_[i][4] = fmaxf(vB.x + sh, 0.f);
        r_[i][5] = fmaxf(vB.y + sh, 0.f);
        r_[i][6] = fmaxf(vB.z + sh, 0.f);
        r_[i][7] = fmaxf(vB.w + sh, 0.f);
    }

    #pragma unroll
    for (int j = 0; j < 8; j++) {
        int cj = tx * 8 + j;
        #pragma unroll
        for (int k = 0; k < 3; k++) {
            int   id = idx_s[cj * 3 + k];
            float w  = w_s[cj * 3 + k];
            const float* src = &g_h1T[((size_t)bb * N1V + id) * COUTV + co0 + ty * 8];
            float4 gA = *(const float4*)&src[0];
            float4 gB = *(const float4*)&src[4];
            r_[0][j] = fmaf(w, gA.x, r_[0][j]);
            r_[1][j] = fmaf(w, gA.y, r_[1][j]);
            r_[2][j] = fmaf(w, gA.z, r_[2][j]);
            r_[3][j] = fmaf(w, gA.w, r_[3][j]);
            r_[4][j] = fmaf(w, gB.x, r_[4][j]);
            r_[5][j] = fmaf(w, gB.y, r_[5][j]);
            r_[6][j] = fmaf(w, gB.z, r_[6][j]);
            r_[7][j] = fmaf(w, gB.w, r_[7][j]);
        }
    }

    #pragma unroll
    for (int i = 0; i < 8; i++) {
        int co = co0 + ty * 8 + i;
        float* drow = &yout[((size_t)(bb * COUTV + co)) * N2V + n0 + tx * 8];
        *(float4*)&drow[0] = make_float4(r_[i][0], r_[i][1], r_[i][2], r_[i][3]);
        *(float4*)&drow[4] = make_float4(r_[i][4], r_[i][5], r_[i][6], r_[i][7]);
    }
}

// ---------------------------------------------------------------------------
extern "C" void kernel_launch(void* const* d_in, const int* in_sizes, int n_in,
                              void* d_out, int out_size)
{
    const float* p1 = (const float*)d_in[0];
    const float* x1 = (const float*)d_in[1];
    const float* p2 = (const float*)d_in[2];
    const float* x2 = (const float*)d_in[3];
    const float* W1 = (const float*)d_in[4];
    const float* g1 = (const float*)d_in[5];
    const float* b1 = (const float*)d_in[6];
    const float* m1 = (const float*)d_in[7];
    const float* v1 = (const float*)d_in[8];
    const float* W2 = (const float*)d_in[9];
    const float* g2 = (const float*)d_in[10];
    const float* b2 = (const float*)d_in[11];
    const float* m2 = (const float*)d_in[12];
    const float* v2 = (const float*)d_in[13];

    float* out = (float*)d_out;
    const int P2SZ = NB * N2V * 3;
    const int YSZ  = NB * COUTV * N2V;

    float* yout = out;
    if (out_size == P2SZ + YSZ) {
        cudaMemcpyAsync(out, p2, (size_t)P2SZ * sizeof(float),
                        cudaMemcpyDeviceToDevice);
        yout = out + P2SZ;
    }

    cudaFuncSetAttribute(front_kernel,
                         cudaFuncAttributeMaxDynamicSharedMemorySize, 32768);
    cudaFuncSetAttribute(conv2_kernel,
                         cudaFuncAttributeMaxDynamicSharedMemorySize, 38400);

    wtrans_kernel<<<dim3(COUTV / 32, CINV / 32, 2), 256>>>(W1, g1, v1, W2, g2, v2);
    front_kernel<<<512, 128, 32768>>>(x1, b1, m1, g1, v1, p1, p2);
    conv2_kernel<<<dim3(N2V / 128, COUTV / 64, NB), 128, 38400>>>(x2, b2, m2, g2, v2, yout);
}